// round 16
// baseline (speedup 1.0000x reference)
#include <cuda_runtime.h>
#include <cstdint>

#define BB 256
#define VV 128000
#define NT 256             // threads per CTA (sweep + tail)
#define HF4 16000          // float4 per half-row
#define GCAP 4096
#define NKEEP 2048
#define NHIST 512
#define TCOL 2.33f
#define LOG2E 1.4426950408889634f
#define SCHRAUD_B 1064866805.0f

__device__ unsigned long long g_cand[BB][GCAP];
__device__ float g_zpart[2 * BB];
__device__ int   g_cnt[BB];      // zero-init; reset by tail CTA each launch
__device__ int   g_done[BB];     // zero-init ticket; reset by tail CTA

__device__ __forceinline__ uint32_t rotl32(uint32_t x, int d) {
    return (x << d) | (x >> (32 - d));
}
__device__ __forceinline__ float ex2f(float x) {
    float r; asm("ex2.approx.f32 %0, %1;" : "=f"(r) : "f"(x)); return r;
}

// JAX partitionable threefry: element i -> threefry2x32(key=(0,42), ctr=(0,i)), out0^out1.
__device__ __forceinline__ uint32_t threefry_bits_part(uint32_t i) {
    uint32_t x0 = 0u, x1 = i;
    const uint32_t k0 = 0u, k1 = 42u;
    const uint32_t k2 = k0 ^ k1 ^ 0x1BD11BDAu;
    x0 += k0; x1 += k1;
#define TF_R(r) { x0 += x1; x1 = rotl32(x1, (r)); x1 ^= x0; }
    TF_R(13) TF_R(15) TF_R(26) TF_R(6)  x0 += k1; x1 += k2 + 1u;
    TF_R(17) TF_R(29) TF_R(16) TF_R(24) x0 += k2; x1 += k0 + 2u;
    TF_R(13) TF_R(15) TF_R(26) TF_R(6)  x0 += k0; x1 += k1 + 3u;
    TF_R(17) TF_R(29) TF_R(16) TF_R(24) x0 += k1; x1 += k2 + 4u;
    TF_R(13) TF_R(15) TF_R(26) TF_R(6)  x0 += k2; x1 += k0 + 5u;
#undef TF_R
    return x0 ^ x1;
}

#define PROC4(cc, qq, zacc)                                                     \
    {                                                                           \
        int i0 = __float2int_rn(fmaf((cc).x, cs, SCHRAUD_B));                   \
        int i1 = __float2int_rn(fmaf((cc).y, cs, SCHRAUD_B));                   \
        int i2 = __float2int_rn(fmaf((cc).z, cs, SCHRAUD_B));                   \
        int i3 = __float2int_rn(fmaf((cc).w, cs, SCHRAUD_B));                   \
        zacc += ((__int_as_float(i0) + __int_as_float(i1))                      \
               + (__int_as_float(i2) + __int_as_float(i3)));                    \
        bool b0 = (cc).x > TCOL, b1 = (cc).y > TCOL,                            \
             b2 = (cc).z > TCOL, b3 = (cc).w > TCOL;                            \
        if (b0 | b1 | b2 | b3) {                                                \
            int cnt = (int)b0 + (int)b1 + (int)b2 + (int)b3;                    \
            int pos = atomicAdd(&s_cnt, cnt);                                   \
            if (b0) { if (pos < NKEEP) s_key[pos] =                             \
                ((unsigned long long)__float_as_uint((cc).x) << 32) |           \
                (unsigned)((qq) * 4 + 0); pos++; }                              \
            if (b1) { if (pos < NKEEP) s_key[pos] =                             \
                ((unsigned long long)__float_as_uint((cc).y) << 32) |           \
                (unsigned)((qq) * 4 + 1); pos++; }                              \
            if (b2) { if (pos < NKEEP) s_key[pos] =                             \
                ((unsigned long long)__float_as_uint((cc).z) << 32) |           \
                (unsigned)((qq) * 4 + 2); pos++; }                              \
            if (b3) { if (pos < NKEEP) s_key[pos] =                             \
                ((unsigned long long)__float_as_uint((cc).w) << 32) |           \
                (unsigned)((qq) * 4 + 3); pos++; }                              \
        }                                                                       \
    }

__global__ void __launch_bounds__(NT, 4) fused_kernel(
    const float* __restrict__ logits,
    const float* __restrict__ a0, const float* __restrict__ a1,
    const float* __restrict__ a2, const float* __restrict__ a3,
    float* __restrict__ out)
{
    __shared__ unsigned long long s_key[NKEEP];   // sweep collect / tail sort
    __shared__ int   s_hist[NHIST];
    __shared__ float s_p[1024];
    __shared__ int   s_idx[1024];
    __shared__ float s_cum[1024];
    __shared__ float s_wscan[NT / 32];
    __shared__ float s_bs[NT / 32];
    __shared__ int   s_bj[NT / 32];
    __shared__ float s_wz[NT / 32];
    __shared__ int   s_cnt, s_base, s_istail, s_gcnt;
    __shared__ int   s_maxbits, s_n2, s_bbin;
    __shared__ int   s_amax[4], s_isint[4];

    const int b    = blockIdx.x >> 1;
    const int half = blockIdx.x & 1;
    const int tid  = threadIdx.x;
    const int lane = tid & 31;
    const int wid  = tid >> 5;      // 0..7

    // ---- input classification (order-agnostic) ----
    const float* arrs[4] = {a0, a1, a2, a3};
    if (tid < 4) { s_amax[tid] = 0; s_isint[tid] = 1; }
    if (tid == 0) { s_cnt = 0; s_maxbits = 0; s_n2 = 0; }
    for (int i = tid; i < NHIST; i += NT) s_hist[i] = 0;
    __syncthreads();
    for (int i = tid; i < 1024; i += NT) {
        int a = i >> 8, e = i & 255;
        float v = arrs[a][e];
        unsigned uv = __float_as_uint(v);
        atomicMax(&s_amax[a], __float_as_int(v));
        if (!(uv >= 1u && uv <= 1024u)) atomicAnd(&s_isint[a], 0);
    }
    __syncthreads();
    int ik = -1, it = -1, ip = -1, im = -1;
    for (int a = 0; a < 4; a++) if (s_isint[a]) ik = a;
    for (int a = 0; a < 4; a++) {
        if (a == ik) continue;
        float mx = __int_as_float(s_amax[a]);
        if (mx >= 1.0f) it = a;
        else if (mx < 0.25f) im = a;
        else ip = a;
    }
    if (ik < 0 || it < 0 || ip < 0 || im < 0) { it = 0; ik = 1; ip = 2; im = 3; }
    const float temp = arrs[it][b];
    const int   topk = reinterpret_cast<const int*>(arrs[ik])[b];
    const float topp = arrs[ip][b];
    const float minp = arrs[im][b];
    const float c0   = LOG2E / temp;
    const float cs   = c0 * 8388608.0f;

    const float4* row4 = reinterpret_cast<const float4*>(logits + (size_t)b * VV);

    // ===== SWEEP of this half (k1 verbatim, NT=256) =====
    {
        const int base = half * HF4;
        float z0 = 0.0f, z1 = 0.0f, z2 = 0.0f, z3 = 0.0f;
#pragma unroll 1
        for (int g = 0; g < 7; g++) {
            int j0 = g * 8;
            float4 c[8];
#pragma unroll
            for (int jj = 0; jj < 8; jj++)
                c[jj] = __ldg(row4 + base + (j0 + jj) * NT + tid);
            PROC4(c[0], base + (j0 + 0) * NT + tid, z0)
            PROC4(c[1], base + (j0 + 1) * NT + tid, z1)
            PROC4(c[2], base + (j0 + 2) * NT + tid, z2)
            PROC4(c[3], base + (j0 + 3) * NT + tid, z3)
            PROC4(c[4], base + (j0 + 4) * NT + tid, z0)
            PROC4(c[5], base + (j0 + 5) * NT + tid, z1)
            PROC4(c[6], base + (j0 + 6) * NT + tid, z2)
            PROC4(c[7], base + (j0 + 7) * NT + tid, z3)
        }
        {
            float4 c[6];
#pragma unroll
            for (int jj = 0; jj < 6; jj++)
                c[jj] = __ldg(row4 + base + (56 + jj) * NT + tid);
            PROC4(c[0], base + 56 * NT + tid, z0)
            PROC4(c[1], base + 57 * NT + tid, z1)
            PROC4(c[2], base + 58 * NT + tid, z2)
            PROC4(c[3], base + 59 * NT + tid, z3)
            PROC4(c[4], base + 60 * NT + tid, z0)
            PROC4(c[5], base + 61 * NT + tid, z1)
        }
        if (tid < 128) {
            float4 ca = __ldg(row4 + base + 62 * NT + tid);
            PROC4(ca, base + 62 * NT + tid, z0)
        }

        float zsum = (z0 + z1) + (z2 + z3);
        for (int o = 16; o; o >>= 1) zsum += __shfl_down_sync(0xffffffffu, zsum, o);
        if (lane == 0) s_wz[wid] = zsum;
        __syncthreads();

        int n_loc = s_cnt;
        if (tid == 0) {
            float z = 0.0f;
            for (int i = 0; i < NT / 32; i++) z += s_wz[i];   // deterministic
            g_zpart[blockIdx.x] = z;
            int add = (n_loc <= NKEEP) ? n_loc : 1000000;
            s_base = atomicAdd(&g_cnt[b], add);
        }
        __syncthreads();
        int nb = s_base;
        int nc = min(n_loc, NKEEP);
        for (int i = tid; i < nc; i += NT)
            if (nb + i < GCAP) g_cand[b][nb + i] = s_key[i];
    }

    // ===== ticket: second finisher runs the tail =====
    __threadfence();            // all threads: flush g_cand/g_zpart writes
    __syncthreads();
    if (tid == 0) {
        int old = atomicAdd(&g_done[b], 1);
        s_istail = (old == 1);
    }
    __syncthreads();
    if (!s_istail) return;      // first finisher exits, frees SM slot
    __threadfence();            // acquire side

    // ===== TAIL (this CTA only; NT=256) =====
    // R15 BUG FIX: single thread reads AND resets g_cnt/g_done; everyone
    // reads the shared copy after a barrier (no read/reset race).
    if (tid == 0) {
        s_gcnt = g_cnt[b];
        g_cnt[b]  = 0;          // reset for next graph replay
        g_done[b] = 0;
    }
    __syncthreads();
    const int cnt = s_gcnt;
    int n2;
    if (cnt >= 1024 && cnt <= NKEEP) {
        n2 = cnt;
        int mxb = 0;
        for (int i = tid; i < NKEEP; i += NT) {
            unsigned long long e = (i < n2) ? g_cand[b][i] : 0ull;
            s_key[i] = e;
            int mb = (int)(unsigned)(e >> 32);
            if (mb > mxb) mxb = mb;
        }
        for (int o = 16; o; o >>= 1) {
            int om = __shfl_down_sync(0xffffffffu, mxb, o);
            if (om > mxb) mxb = om;
        }
        if (lane == 0) atomicMax(&s_maxbits, mxb);
        __syncthreads();
        float z = g_zpart[2 * b] + g_zpart[2 * b + 1];   // fixed order
        const float Mraw = __int_as_float(s_maxbits);
        const float m    = Mraw / temp;
        const float Zs   = z * ex2f(-Mraw * c0);
        for (int i = tid; i < NKEEP; i += NT) {
            unsigned long long e = s_key[i];
            unsigned long long kk = 0ull;
            if (i < n2) {
                float l = __uint_as_float((unsigned)(e >> 32));
                float x = l / temp;
                float p = expf(x - m) / Zs;
                kk = ((unsigned long long)__float_as_uint(p) << 32)
                     | (unsigned)(e & 0xffffffffu);
            }
            s_key[i] = kk;
        }
    } else {
        // ===== COLD FALLBACK: full re-sweep via LDG (correctness only) =====
        const int N4 = VV / 4;
        float mxl = -3.402823466e38f;
        for (int q = tid; q < N4; q += NT) {
            float4 c = __ldg(row4 + q);
            mxl = fmaxf(mxl, fmaxf(fmaxf(c.x, c.y), fmaxf(c.z, c.w)));
        }
        for (int o = 16; o; o >>= 1)
            mxl = fmaxf(mxl, __shfl_down_sync(0xffffffffu, mxl, o));
        if (lane == 0) atomicMax(&s_maxbits, __float_as_int(mxl));
        __syncthreads();
        const float Mr = __int_as_float(s_maxbits);
        float zl = 0.0f;
        for (int q = tid; q < N4; q += NT) {
            float4 c = __ldg(row4 + q);
#pragma unroll
            for (int u = 0; u < 4; u++) {
                float lx = (u == 0) ? c.x : (u == 1) ? c.y : (u == 2) ? c.z : c.w;
                zl += __int_as_float(__float2int_rn(fmaf(lx, cs, SCHRAUD_B)));
                float d = Mr - lx;
                if (d < 16.0f) atomicAdd(&s_hist[(int)(d * 32.0f)], 1);
            }
        }
        for (int o = 16; o; o >>= 1) zl += __shfl_down_sync(0xffffffffu, zl, o);
        if (lane == 0) s_wscan[wid] = zl;
        __syncthreads();
        if (tid == 0) {
            int cum = 0, bbv = NHIST - 1;
            for (int k = 0; k < NHIST; k++) {
                cum += s_hist[k];
                if (cum >= 1024) { bbv = k; break; }
            }
            s_bbin = bbv;
            float z = 0.0f;
            for (int i = 0; i < NT / 32; i++) z += s_wscan[i];
            s_p[1] = z;
        }
        __syncthreads();
        const int bbv = s_bbin;
        for (int q = tid; q < N4; q += NT) {
            float4 c = __ldg(row4 + q);
#pragma unroll
            for (int u = 0; u < 4; u++) {
                float lx = (u == 0) ? c.x : (u == 1) ? c.y : (u == 2) ? c.z : c.w;
                float d = Mr - lx;
                bool kp = (d < 16.0f) && ((int)(d * 32.0f) <= bbv);
                if (kp) {
                    int pos = atomicAdd(&s_n2, 1);
                    if (pos < NKEEP)
                        s_key[pos] = ((unsigned long long)__float_as_uint(lx) << 32)
                                     | (unsigned)(q * 4 + u);
                }
            }
        }
        __syncthreads();
        n2 = min(s_n2, NKEEP);
        const float m  = Mr / temp;
        const float Zs = s_p[1] * ex2f(-Mr * c0);
        for (int i = tid; i < NKEEP; i += NT) {
            unsigned long long kk = 0ull;
            if (i < n2) {
                unsigned long long e = s_key[i];
                float l = __uint_as_float((unsigned)(e >> 32));
                float x = l / temp;
                float p = expf(x - m) / Zs;
                kk = ((unsigned long long)__float_as_uint(p) << 32)
                     | (unsigned)(e & 0xffffffffu);
            }
            s_key[i] = kk;
        }
    }

    // ===== bitonic sort desc over 2048 keys (4 pairs/thread/phase) =====
    for (unsigned size = 2; size <= (unsigned)NKEEP; size <<= 1) {
        for (unsigned stride = size >> 1; stride > 0; stride >>= 1) {
            __syncthreads();
#pragma unroll
            for (int r = 0; r < 4; r++) {
                unsigned t = (unsigned)tid + r * NT;
                unsigned pos = 2 * t - (t & (stride - 1));
                unsigned long long va = s_key[pos];
                unsigned long long vb = s_key[pos + stride];
                bool desc = ((pos & size) == 0);
                bool sw = desc ? (va < vb) : (va > vb);
                if (sw) { s_key[pos] = vb; s_key[pos + stride] = va; }
            }
        }
    }
    __syncthreads();

    for (int i = tid; i < 1024; i += NT) {
        unsigned long long kk = s_key[i];
        s_p[i]   = __uint_as_float((unsigned)(kk >> 32));
        s_idx[i] = (int)(kk & 0xffffffffu);
    }
    __syncthreads();

    // ===== inclusive prefix sum over 1024 probs (4 elems/thread + shfl) =====
    {
        float v0 = s_p[4 * tid], v1 = s_p[4 * tid + 1];
        float v2 = s_p[4 * tid + 2], v3 = s_p[4 * tid + 3];
        float p01 = v0 + v1, p012 = p01 + v2, tsum = p012 + v3;
        float incl = tsum;
#pragma unroll
        for (int o = 1; o < 32; o <<= 1) {
            float t = __shfl_up_sync(0xffffffffu, incl, o);
            if (lane >= o) incl += t;
        }
        if (lane == 31) s_wscan[wid] = incl;
        __syncthreads();
        if (wid == 0) {
            float w = (lane < NT / 32) ? s_wscan[lane] : 0.0f;
            float wincl = w;
#pragma unroll
            for (int o = 1; o < 32; o <<= 1) {
                float t = __shfl_up_sync(0xffffffffu, wincl, o);
                if (lane >= o) wincl += t;
            }
            if (lane < NT / 32) s_wscan[lane] = wincl - w;
        }
        __syncthreads();
        float base = s_wscan[wid] + (incl - tsum);
        s_cum[4 * tid]     = base + v0;
        s_cum[4 * tid + 1] = base + p01;
        s_cum[4 * tid + 2] = base + p012;
        s_cum[4 * tid + 3] = base + tsum;
    }
    __syncthreads();

    // ===== masks + Gumbel argmax (j = tid + h*NT, h=0..3) =====
    const float thrmp = s_p[0] * minp;
    float score = -3.402823466e38f;
    int   bj    = 0;
#pragma unroll
    for (int h = 0; h < 4; h++) {
        int j = tid + h * NT;
        if (j < topk) {
            float pj   = s_p[j];
            float excl = s_cum[j] - pj;
            if (!(excl > topp) && !(pj < thrmp) && pj > 0.0f) {
                unsigned i = (unsigned)b * (unsigned)VV + (unsigned)j;
                unsigned bits = threefry_bits_part(i);
                float f = __uint_as_float((bits >> 9) | 0x3f800000u) - 1.0f;
                float uu = fmaxf(f + 1.1754943508222875e-38f, 1.1754943508222875e-38f);
                float g = -logf(-logf(uu));
                float sc = g + logf(pj);
                if (sc > score || (sc == score && j < bj)) { score = sc; bj = j; }
            }
        }
    }
    for (int o = 16; o; o >>= 1) {
        float os = __shfl_down_sync(0xffffffffu, score, o);
        int   oj = __shfl_down_sync(0xffffffffu, bj, o);
        if (os > score || (os == score && oj < bj)) { score = os; bj = oj; }
    }
    if (lane == 0) { s_bs[wid] = score; s_bj[wid] = bj; }
    __syncthreads();
    if (tid == 0) {
        float bsc = s_bs[0]; int bjj = s_bj[0];
        for (int i = 1; i < NT / 32; i++) {
            if (s_bs[i] > bsc || (s_bs[i] == bsc && s_bj[i] < bjj)) {
                bsc = s_bs[i]; bjj = s_bj[i];
            }
        }
        out[b]      = (float)s_idx[bjj];
        out[BB + b] = logf(s_p[bjj]);
    }
}

extern "C" void kernel_launch(void* const* d_in, const int* in_sizes, int n_in,
                              void* d_out, int out_size) {
    (void)out_size;
    int li = 0;
    for (int i = 0; i < n_in; i++) if (in_sizes[i] > 100000) li = i;
    const float* small[4];
    int ns = 0;
    for (int i = 0; i < n_in && ns < 4; i++)
        if (i != li) small[ns++] = (const float*)d_in[i];
    fused_kernel<<<2 * BB, NT>>>(
        (const float*)d_in[li],
        small[0], small[1], small[2], small[3],
        (float*)d_out);
}

// round 17
// speedup vs baseline: 1.9266x; 1.9266x over previous
#include <cuda_runtime.h>
#include <cstdint>

#define BB 256
#define VV 128000
#define NT1 256
#define NT2 512
#define HF4 16000          // float4 per half-row
#define GCAP 4096
#define NKEEP 2048
#define NBINS 1024
#define TCOL 2.33f
#define LOG2E 1.4426950408889634f
#define SCHRAUD_B 1064866805.0f

__device__ unsigned long long g_cand[BB][GCAP];
__device__ float g_zpart[2 * BB];
__device__ int   g_cnt[BB];          // zero-init; k2 resets each replay

__device__ __forceinline__ uint32_t rotl32(uint32_t x, int d) {
    return (x << d) | (x >> (32 - d));
}
__device__ __forceinline__ float ex2f(float x) {
    float r; asm("ex2.approx.f32 %0, %1;" : "=f"(r) : "f"(x)); return r;
}

// JAX partitionable threefry: element i -> threefry2x32(key=(0,42), ctr=(0,i)), out0^out1.
__device__ __forceinline__ uint32_t threefry_bits_part(uint32_t i) {
    uint32_t x0 = 0u, x1 = i;
    const uint32_t k0 = 0u, k1 = 42u;
    const uint32_t k2 = k0 ^ k1 ^ 0x1BD11BDAu;
    x0 += k0; x1 += k1;
#define TF_R(r) { x0 += x1; x1 = rotl32(x1, (r)); x1 ^= x0; }
    TF_R(13) TF_R(15) TF_R(26) TF_R(6)  x0 += k1; x1 += k2 + 1u;
    TF_R(17) TF_R(29) TF_R(16) TF_R(24) x0 += k2; x1 += k0 + 2u;
    TF_R(13) TF_R(15) TF_R(26) TF_R(6)  x0 += k0; x1 += k1 + 3u;
    TF_R(17) TF_R(29) TF_R(16) TF_R(24) x0 += k1; x1 += k2 + 4u;
    TF_R(13) TF_R(15) TF_R(26) TF_R(6)  x0 += k2; x1 += k0 + 5u;
#undef TF_R
    return x0 ^ x1;
}

#define CLASSIFY_BLOCK(NTHR)                                                    \
    const float* arrs[4] = {a0, a1, a2, a3};                                    \
    if (tid < 4) { s_amax[tid] = 0; s_isint[tid] = 1; }                         \
    __syncthreads();                                                            \
    for (int i = tid; i < 1024; i += (NTHR)) {                                  \
        int a = i >> 8, e = i & 255;                                            \
        float v = arrs[a][e];                                                   \
        unsigned uv = __float_as_uint(v);                                       \
        atomicMax(&s_amax[a], __float_as_int(v));                               \
        if (!(uv >= 1u && uv <= 1024u)) atomicAnd(&s_isint[a], 0);              \
    }                                                                           \
    __syncthreads();                                                            \
    int ik = -1, it = -1, ip = -1, im = -1;                                     \
    for (int a = 0; a < 4; a++) if (s_isint[a]) ik = a;                         \
    for (int a = 0; a < 4; a++) {                                               \
        if (a == ik) continue;                                                  \
        float mx = __int_as_float(s_amax[a]);                                   \
        if (mx >= 1.0f) it = a;                                                 \
        else if (mx < 0.25f) im = a;                                            \
        else ip = a;                                                            \
    }                                                                           \
    if (ik < 0 || it < 0 || ip < 0 || im < 0) { it = 0; ik = 1; ip = 2; im = 3; }

#define PROC4(cc, qq, zacc)                                                     \
    {                                                                           \
        int i0 = __float2int_rn(fmaf((cc).x, cs, SCHRAUD_B));                   \
        int i1 = __float2int_rn(fmaf((cc).y, cs, SCHRAUD_B));                   \
        int i2 = __float2int_rn(fmaf((cc).z, cs, SCHRAUD_B));                   \
        int i3 = __float2int_rn(fmaf((cc).w, cs, SCHRAUD_B));                   \
        zacc += ((__int_as_float(i0) + __int_as_float(i1))                      \
               + (__int_as_float(i2) + __int_as_float(i3)));                    \
        bool b0 = (cc).x > TCOL, b1 = (cc).y > TCOL,                            \
             b2 = (cc).z > TCOL, b3 = (cc).w > TCOL;                            \
        if (b0 | b1 | b2 | b3) {                                                \
            int cnt = (int)b0 + (int)b1 + (int)b2 + (int)b3;                    \
            int pos = atomicAdd(&s_cnt, cnt);                                   \
            if (b0) { if (pos < NKEEP) s_key[pos] =                             \
                ((unsigned long long)__float_as_uint((cc).x) << 32) |           \
                (unsigned)((qq) * 4 + 0); pos++; }                              \
            if (b1) { if (pos < NKEEP) s_key[pos] =                             \
                ((unsigned long long)__float_as_uint((cc).y) << 32) |           \
                (unsigned)((qq) * 4 + 1); pos++; }                              \
            if (b2) { if (pos < NKEEP) s_key[pos] =                             \
                ((unsigned long long)__float_as_uint((cc).z) << 32) |           \
                (unsigned)((qq) * 4 + 2); pos++; }                              \
            if (b3) { if (pos < NKEEP) s_key[pos] =                             \
                ((unsigned long long)__float_as_uint((cc).w) << 32) |           \
                (unsigned)((qq) * 4 + 3); pos++; }                              \
        }                                                                       \
    }

// ===================== k1: pure sweep, 2 CTAs per row (R12 verbatim, 27us) =====================
__global__ void __launch_bounds__(NT1, 4) k1_sweep(
    const float* __restrict__ logits,
    const float* __restrict__ a0, const float* __restrict__ a1,
    const float* __restrict__ a2, const float* __restrict__ a3)
{
    __shared__ unsigned long long s_key[NKEEP];
    __shared__ float s_wz[NT1 / 32];
    __shared__ int   s_cnt, s_base;
    __shared__ int   s_amax[4], s_isint[4];

    const int b    = blockIdx.x >> 1;
    const int half = blockIdx.x & 1;
    const int tid  = threadIdx.x;
    const int lane = tid & 31;
    const int wid  = tid >> 5;

    if (tid == 0) s_cnt = 0;
    CLASSIFY_BLOCK(NT1)
    const float temp = arrs[it][b];
    const float c0   = LOG2E / temp;
    const float cs   = c0 * 8388608.0f;

    const float4* row4 = reinterpret_cast<const float4*>(logits + (size_t)b * VV);
    const int base = half * HF4;

    float z0 = 0.0f, z1 = 0.0f, z2 = 0.0f, z3 = 0.0f;
#pragma unroll 1
    for (int g = 0; g < 7; g++) {
        int j0 = g * 8;
        float4 c[8];
#pragma unroll
        for (int jj = 0; jj < 8; jj++)
            c[jj] = __ldg(row4 + base + (j0 + jj) * NT1 + tid);
        PROC4(c[0], base + (j0 + 0) * NT1 + tid, z0)
        PROC4(c[1], base + (j0 + 1) * NT1 + tid, z1)
        PROC4(c[2], base + (j0 + 2) * NT1 + tid, z2)
        PROC4(c[3], base + (j0 + 3) * NT1 + tid, z3)
        PROC4(c[4], base + (j0 + 4) * NT1 + tid, z0)
        PROC4(c[5], base + (j0 + 5) * NT1 + tid, z1)
        PROC4(c[6], base + (j0 + 6) * NT1 + tid, z2)
        PROC4(c[7], base + (j0 + 7) * NT1 + tid, z3)
    }
    {
        float4 c[6];
#pragma unroll
        for (int jj = 0; jj < 6; jj++)
            c[jj] = __ldg(row4 + base + (56 + jj) * NT1 + tid);
        PROC4(c[0], base + 56 * NT1 + tid, z0)
        PROC4(c[1], base + 57 * NT1 + tid, z1)
        PROC4(c[2], base + 58 * NT1 + tid, z2)
        PROC4(c[3], base + 59 * NT1 + tid, z3)
        PROC4(c[4], base + 60 * NT1 + tid, z0)
        PROC4(c[5], base + 61 * NT1 + tid, z1)
    }
    if (tid < 128) {
        float4 ca = __ldg(row4 + base + 62 * NT1 + tid);
        PROC4(ca, base + 62 * NT1 + tid, z0)
    }

    float zsum = (z0 + z1) + (z2 + z3);
    for (int o = 16; o; o >>= 1) zsum += __shfl_down_sync(0xffffffffu, zsum, o);
    if (lane == 0) s_wz[wid] = zsum;
    __syncthreads();

    int n_loc = s_cnt;
    if (tid == 0) {
        float z = 0.0f;
        for (int i = 0; i < NT1 / 32; i++) z += s_wz[i];
        g_zpart[blockIdx.x] = z;
        int add = (n_loc <= NKEEP) ? n_loc : 1000000;
        s_base = atomicAdd(&g_cnt[b], add);
    }
    __syncthreads();
    int nb = s_base;
    int nc = min(n_loc, NKEEP);
    for (int i = tid; i < nc; i += NT1)
        if (nb + i < GCAP) g_cand[b][nb + i] = s_key[i];
}

// ===================== k2: tail with O(n) bucket sort =====================
__global__ void __launch_bounds__(NT2, 2) k2_tail(
    const float* __restrict__ logits,
    const float* __restrict__ a0, const float* __restrict__ a1,
    const float* __restrict__ a2, const float* __restrict__ a3,
    float* __restrict__ out)
{
    __shared__ unsigned long long s_src[NKEEP];   // raw (l,idx) -> (p,idx); later overlay p/idx/cum
    __shared__ unsigned long long s_key[NKEEP];   // bucket-scatter dest (sorted)
    __shared__ unsigned short s_bin[NKEEP];
    __shared__ int   s_hist[NBINS];               // counts, then countdown cursor
    __shared__ int   s_start[NBINS + 1];
    __shared__ int   s_iw[NT2 / 32];
    __shared__ float s_wscan[NT2 / 32];
    __shared__ float s_bs[NT2 / 32];
    __shared__ int   s_bj[NT2 / 32];
    __shared__ int   s_maxbits, s_n2, s_bbin;
    __shared__ float s_zfb, s_scale;
    __shared__ int   s_amax[4], s_isint[4];

    float* s_p   = reinterpret_cast<float*>(s_src);          // [0,1024)
    int*   s_idx = reinterpret_cast<int*>(s_src) + 1024;     // [1024,2048)
    float* s_cum = reinterpret_cast<float*>(s_src) + 2048;   // [2048,3072)

    const int b    = blockIdx.x;
    const int tid  = threadIdx.x;
    const int lane = tid & 31;
    const int wid  = tid >> 5;          // 0..15

    if (tid == 0) { s_maxbits = 0; s_n2 = 0; }
    for (int i = tid; i < NBINS; i += NT2) s_hist[i] = 0;
    CLASSIFY_BLOCK(NT2)
    const float temp = arrs[it][b];
    const int   topk = reinterpret_cast<const int*>(arrs[ik])[b];
    const float topp = arrs[ip][b];
    const float minp = arrs[im][b];
    const float c0   = LOG2E / temp;

    int cnt = g_cnt[b];
    int n2;
    if (cnt >= 1024 && cnt <= NKEEP) {
        // ---- normal path: load raw (l,idx) keys, find row max ----
        n2 = cnt;
        int mxb = 0;
        for (int i = tid; i < n2; i += NT2) {
            unsigned long long e = g_cand[b][i];
            s_src[i] = e;
            int mb = (int)(unsigned)(e >> 32);
            if (mb > mxb) mxb = mb;
        }
        for (int o = 16; o; o >>= 1) {
            int om = __shfl_down_sync(0xffffffffu, mxb, o);
            if (om > mxb) mxb = om;
        }
        if (lane == 0) atomicMax(&s_maxbits, mxb);
        __syncthreads();
        if (tid == 0) {
            g_cnt[b] = 0;                               // reset for next replay
            s_zfb    = g_zpart[2 * b] + g_zpart[2 * b + 1];   // fixed order
            float Mraw = __int_as_float(s_maxbits);
            s_scale  = (float)NBINS / (Mraw - TCOL + 1e-4f);
        }
        __syncthreads();
    } else {
        // ---- COLD FALLBACK: full re-sweep (correctness only) ----
        if (tid == 0) g_cnt[b] = 0;
        const float4* row4 = reinterpret_cast<const float4*>(logits + (size_t)b * VV);
        const int N4 = VV / 4;
        const float cs = c0 * 8388608.0f;
        float mxl = -3.402823466e38f;
        for (int q = tid; q < N4; q += NT2) {
            float4 c = __ldg(row4 + q);
            mxl = fmaxf(mxl, fmaxf(fmaxf(c.x, c.y), fmaxf(c.z, c.w)));
        }
        for (int o = 16; o; o >>= 1)
            mxl = fmaxf(mxl, __shfl_down_sync(0xffffffffu, mxl, o));
        if (lane == 0) atomicMax(&s_maxbits, __float_as_int(mxl));
        __syncthreads();
        const float Mr = __int_as_float(s_maxbits);
        float zl = 0.0f;
        for (int q = tid; q < N4; q += NT2) {
            float4 c = __ldg(row4 + q);
#pragma unroll
            for (int u = 0; u < 4; u++) {
                float lx = (u == 0) ? c.x : (u == 1) ? c.y : (u == 2) ? c.z : c.w;
                zl += __int_as_float(__float2int_rn(fmaf(lx, cs, SCHRAUD_B)));
                float d = Mr - lx;
                if (d < 16.0f) atomicAdd(&s_hist[(int)(d * 32.0f)], 1);  // 512 bins used
            }
        }
        for (int o = 16; o; o >>= 1) zl += __shfl_down_sync(0xffffffffu, zl, o);
        if (lane == 0) s_wscan[wid] = zl;
        __syncthreads();
        if (tid == 0) {
            int cum = 0, bbv = 511;
            for (int k = 0; k < 512; k++) {
                cum += s_hist[k];
                if (cum >= 1024) { bbv = k; break; }
            }
            s_bbin = bbv;
            float z = 0.0f;
            for (int i = 0; i < NT2 / 32; i++) z += s_wscan[i];
            s_zfb = z;
            s_scale = (float)NBINS / ((float)(bbv + 1) / 32.0f + 1e-4f);
        }
        __syncthreads();
        const int bbv = s_bbin;
        for (int q = tid; q < N4; q += NT2) {
            float4 c = __ldg(row4 + q);
#pragma unroll
            for (int u = 0; u < 4; u++) {
                float lx = (u == 0) ? c.x : (u == 1) ? c.y : (u == 2) ? c.z : c.w;
                float d = Mr - lx;
                bool kp = (d < 16.0f) && ((int)(d * 32.0f) <= bbv);
                if (kp) {
                    int pos = atomicAdd(&s_n2, 1);
                    if (pos < NKEEP)
                        s_src[pos] = ((unsigned long long)__float_as_uint(lx) << 32)
                                     | (unsigned)(q * 4 + u);
                }
            }
        }
        __syncthreads();
        n2 = min(s_n2, NKEEP);
        // re-zero hist for bucket pipeline (fallback dirtied 512 bins)
        for (int i = tid; i < NBINS; i += NT2) s_hist[i] = 0;
        __syncthreads();
    }

    const float Mraw  = __int_as_float(s_maxbits);
    const float m     = Mraw / temp;                 // bit-exact max(l/temp)
    const float Zs    = s_zfb * ex2f(-Mraw * c0);
    const float scale = s_scale;

    // ===== pass A: convert raw->(p,idx), bin, histogram; prefill dest =====
    for (int i = tid; i < NKEEP; i += NT2) {
        if (i < n2) {
            unsigned long long e = s_src[i];
            float l = __uint_as_float((unsigned)(e >> 32));
            float x = l / temp;
            float p = expf(x - m) / Zs;              // bit-exact p arithmetic
            int bin = (int)((Mraw - l) * scale);
            bin = min(max(bin, 0), NBINS - 1);
            s_bin[i] = (unsigned short)bin;
            atomicAdd(&s_hist[bin], 1);
            s_src[i] = ((unsigned long long)__float_as_uint(p) << 32)
                       | (unsigned)(e & 0xffffffffu);
        }
        s_key[i] = 0ull;                             // pad
    }
    __syncthreads();

    // ===== exclusive prefix scan over NBINS=1024 bins (2 bins/thread) =====
    {
        int b0 = 2 * tid, b1 = b0 + 1;
        int c0v = s_hist[b0], c1v = s_hist[b1];
        int ssum = c0v + c1v;
        int incl = ssum;
#pragma unroll
        for (int o = 1; o < 32; o <<= 1) {
            int t = __shfl_up_sync(0xffffffffu, incl, o);
            if (lane >= o) incl += t;
        }
        if (lane == 31) s_iw[wid] = incl;
        __syncthreads();
        if (wid == 0) {
            int w = (lane < NT2 / 32) ? s_iw[lane] : 0;
            int wincl = w;
#pragma unroll
            for (int o = 1; o < 32; o <<= 1) {
                int t = __shfl_up_sync(0xffffffffu, wincl, o);
                if (lane >= o) wincl += t;
            }
            if (lane < NT2 / 32) s_iw[lane] = wincl - w;
        }
        __syncthreads();
        int basex = s_iw[wid] + (incl - ssum);
        s_start[b0] = basex;
        s_start[b1] = basex + c0v;
        if (tid == NT2 - 1) s_start[NBINS] = basex + ssum;
    }
    __syncthreads();

    // ===== pass B: scatter (s_hist as countdown cursor) =====
    for (int i = tid; i < n2; i += NT2) {
        int bin = s_bin[i];
        int v = atomicSub(&s_hist[bin], 1);
        s_key[s_start[bin] + v - 1] = s_src[i];
    }
    __syncthreads();

    // ===== pass C: per-bucket insertion sort, desc by u64 (p,idx) =====
    for (int bin = tid; bin < NBINS; bin += NT2) {
        int st = s_start[bin], en = s_start[bin + 1];
        for (int a2q = st + 1; a2q < en; a2q++) {
            unsigned long long v = s_key[a2q];
            int bp = a2q - 1;
            while (bp >= st && s_key[bp] < v) { s_key[bp + 1] = s_key[bp]; bp--; }
            s_key[bp + 1] = v;
        }
    }
    __syncthreads();

    // ===== top-1024 -> (p, idx) [overlays s_src] =====
    for (int i = tid; i < 1024; i += NT2) {
        unsigned long long kk = s_key[i];
        float pv = __uint_as_float((unsigned)(kk >> 32));
        int   iv = (int)(kk & 0xffffffffu);
        __syncthreads();   // s_src fully dead before overlay write
        s_p[i]   = pv;
        s_idx[i] = iv;
    }
    __syncthreads();

    // ===== inclusive prefix sum over 1024 sorted probs (2 elems/thread) =====
    {
        float va = s_p[2 * tid];
        float vb = s_p[2 * tid + 1];
        float sp = va + vb;
        float incl = sp;
#pragma unroll
        for (int o = 1; o < 32; o <<= 1) {
            float t = __shfl_up_sync(0xffffffffu, incl, o);
            if (lane >= o) incl += t;
        }
        if (lane == 31) s_wscan[wid] = incl;
        __syncthreads();
        if (wid == 0) {
            float w = (lane < NT2 / 32) ? s_wscan[lane] : 0.0f;
            float wincl = w;
#pragma unroll
            for (int o = 1; o < 32; o <<= 1) {
                float t = __shfl_up_sync(0xffffffffu, wincl, o);
                if (lane >= o) wincl += t;
            }
            if (lane < NT2 / 32) s_wscan[lane] = wincl - w;
        }
        __syncthreads();
        float basex = s_wscan[wid] + (incl - sp);
        s_cum[2 * tid]     = basex + va;
        s_cum[2 * tid + 1] = basex + va + vb;
    }
    __syncthreads();

    // ===== masks + Gumbel argmax (j = tid, tid+NT2) =====
    const float thrmp = s_p[0] * minp;
    float score = -3.402823466e38f;
    int   bj    = 0;
#pragma unroll
    for (int h = 0; h < 2; h++) {
        int j = tid + h * NT2;
        if (j < topk) {
            float pj   = s_p[j];
            float excl = s_cum[j] - pj;
            if (!(excl > topp) && !(pj < thrmp) && pj > 0.0f) {
                unsigned i = (unsigned)b * (unsigned)VV + (unsigned)j;
                unsigned bits = threefry_bits_part(i);
                float f = __uint_as_float((bits >> 9) | 0x3f800000u) - 1.0f;
                float uu = fmaxf(f + 1.1754943508222875e-38f, 1.1754943508222875e-38f);
                float g = -logf(-logf(uu));
                float sc = g + logf(pj);
                if (sc > score || (sc == score && j < bj)) { score = sc; bj = j; }
            }
        }
    }
    for (int o = 16; o; o >>= 1) {
        float os = __shfl_down_sync(0xffffffffu, score, o);
        int   oj = __shfl_down_sync(0xffffffffu, bj, o);
        if (os > score || (os == score && oj < bj)) { score = os; bj = oj; }
    }
    if (lane == 0) { s_bs[wid] = score; s_bj[wid] = bj; }
    __syncthreads();
    if (tid == 0) {
        float bsc = s_bs[0]; int bjj = s_bj[0];
        for (int i = 1; i < NT2 / 32; i++) {
            if (s_bs[i] > bsc || (s_bs[i] == bsc && s_bj[i] < bjj)) {
                bsc = s_bs[i]; bjj = s_bj[i];
            }
        }
        out[b]      = (float)s_idx[bjj];
        out[BB + b] = logf(s_p[bjj]);
    }
}

extern "C" void kernel_launch(void* const* d_in, const int* in_sizes, int n_in,
                              void* d_out, int out_size) {
    (void)out_size;
    int li = 0;
    for (int i = 0; i < n_in; i++) if (in_sizes[i] > 100000) li = i;
    const float* small[4];
    int ns = 0;
    for (int i = 0; i < n_in && ns < 4; i++)
        if (i != li) small[ns++] = (const float*)d_in[i];
    const float* lg = (const float*)d_in[li];
    k1_sweep<<<2 * BB, NT1>>>(lg, small[0], small[1], small[2], small[3]);
    k2_tail<<<BB, NT2>>>(lg, small[0], small[1], small[2], small[3], (float*)d_out);
}